// round 1
// baseline (speedup 1.0000x reference)
#include <cuda_runtime.h>
#include <math.h>

#define NN 100000
#define EE 3200000
#define CHUNK 6400000      // 64*NN
#define TOTXM 38400000     // 384*NN

// ---------------- scratch (device globals; no allocation) ----------------
__device__ float d_h[NN * 64];          // GEMM output / layer input features
__device__ float d_acc[NN * 64];        // scatter accumulator
__device__ float d_xm[(size_t)NN * 384]; // XM flat [N, 384] row-major
__device__ float d_deg[NN];
__device__ float d_dinv[NN];
__device__ float d_norm[EE];
__device__ float d_sums[8];
__device__ float d_coef[8];

// ---------------- small utility kernels ----------------
__global__ void k_init_deg() {
    int t = blockIdx.x * blockDim.x + threadIdx.x;
    if (t < NN) d_deg[t] = 1.0f;  // self-loop weight
}

__global__ void k_zero_acc() {
    int t = blockIdx.x * blockDim.x + threadIdx.x;
    if (t < NN * 64) d_acc[t] = 0.0f;
}

__global__ void k_zero_sums() {
    if (threadIdx.x < 8) d_sums[threadIdx.x] = 0.0f;
}

__global__ void k_deg(const int* __restrict__ ei, const float* __restrict__ ew) {
    int e = blockIdx.x * blockDim.x + threadIdx.x;
    if (e < EE) atomicAdd(&d_deg[ei[EE + e]], ew[e]);
}

__global__ void k_dinv() {
    int t = blockIdx.x * blockDim.x + threadIdx.x;
    if (t < NN) {
        float dg = d_deg[t];
        d_dinv[t] = (dg > 0.0f) ? rsqrtf(dg) : 0.0f;
    }
}

__global__ void k_norm(const int* __restrict__ ei, const float* __restrict__ ew) {
    int e = blockIdx.x * blockDim.x + threadIdx.x;
    if (e < EE) d_norm[e] = d_dinv[ei[e]] * ew[e] * d_dinv[ei[EE + e]];
}

// ---------------- GEMM: out[N,64] = in[N,64(stride)] @ W[64,64] ----------------
// Block: 256 threads, tile 128 rows x 64 cols. Each thread: 8 rows x 4 cols.
__global__ void k_gemm(const float* __restrict__ in_ext, int stride, int off,
                       const float* __restrict__ W) {
    __shared__ float sW[64 * 64];     // 16 KB
    __shared__ float sX[128 * 64];    // 32 KB
    const float* in = in_ext ? in_ext : d_xm;
    int t = threadIdx.x;

    #pragma unroll
    for (int i = t; i < 1024; i += 256)
        ((float4*)sW)[i] = ((const float4*)W)[i];

    int r0 = blockIdx.x * 128;
    for (int i = t; i < 2048; i += 256) {
        int r = i >> 4, k4 = i & 15;
        int row = r0 + r;
        float4 v = make_float4(0.f, 0.f, 0.f, 0.f);
        if (row < NN)
            v = *(const float4*)&in[(size_t)row * stride + off + k4 * 4];
        ((float4*)sX)[r * 16 + k4] = v;
    }
    __syncthreads();

    int j4 = (t & 15) * 4;
    int rg = t >> 4;
    float acc[8][4];
    #pragma unroll
    for (int a = 0; a < 8; a++)
        #pragma unroll
        for (int b = 0; b < 4; b++) acc[a][b] = 0.f;

    #pragma unroll
    for (int k = 0; k < 64; k++) {
        float4 w = *(float4*)&sW[k * 64 + j4];
        #pragma unroll
        for (int a = 0; a < 8; a++) {
            float xv = sX[(rg + 16 * a) * 64 + k];
            acc[a][0] += xv * w.x;
            acc[a][1] += xv * w.y;
            acc[a][2] += xv * w.z;
            acc[a][3] += xv * w.w;
        }
    }
    #pragma unroll
    for (int a = 0; a < 8; a++) {
        int row = r0 + rg + 16 * a;
        if (row < NN)
            *(float4*)&d_h[row * 64 + j4] =
                make_float4(acc[a][0], acc[a][1], acc[a][2], acc[a][3]);
    }
}

// ---------------- edge scatter: acc[col] += h[row] * norm (v4 reductions) --------
__global__ void k_scatter(const int* __restrict__ ei) {
    int t = blockIdx.x * blockDim.x + threadIdx.x;
    int e = t >> 4, q = t & 15;
    if (e >= EE) return;
    int row = ei[e];
    int col = ei[EE + e];
    float nm = d_norm[e];
    float4 hv = ((const float4*)d_h)[row * 16 + q];
    float4* p = ((float4*)d_acc) + col * 16 + q;
    asm volatile("red.global.add.v4.f32 [%0], {%1, %2, %3, %4};"
                 :: "l"(p), "f"(hv.x * nm), "f"(hv.y * nm),
                    "f"(hv.z * nm), "f"(hv.w * nm)
                 : "memory");
}

// ---------------- epilogue: self-loop + bias + relu, write into XM slice --------
__global__ void k_epi(const float* __restrict__ b, int off) {
    int t = blockIdx.x * blockDim.x + threadIdx.x;
    if (t >= NN * 64) return;
    int n = t >> 6, j = t & 63;
    float sn = d_dinv[n];
    sn *= sn;
    float v = d_acc[t] + d_h[t] * sn + b[j];
    d_xm[(size_t)n * 384 + off + j] = fmaxf(v, 0.0f);
}

// ---------------- chunk sums over flat XM (6 contiguous ranges of 6.4M) --------
__global__ void k_chunksum() {
    __shared__ float ss[6];
    int t = threadIdx.x;
    if (t < 6) ss[t] = 0.0f;
    __syncthreads();
    int stride = gridDim.x * blockDim.x;
    int cur = -1;
    float s = 0.0f;
    for (int idx = blockIdx.x * blockDim.x + t; idx < TOTXM; idx += stride) {
        int c = idx / CHUNK;   // monotonic non-decreasing per thread
        if (c != cur) {
            if (cur >= 0) atomicAdd(&ss[cur], s);
            cur = c; s = 0.0f;
        }
        s += d_xm[idx];
    }
    if (cur >= 0) atomicAdd(&ss[cur], s);
    __syncthreads();
    if (t < 6) atomicAdd(&d_sums[t], ss[t]);
}

// ---------------- SE attention (tiny) -> per-chunk coefficients ----------------
__global__ void k_att(const float* __restrict__ f1w, const float* __restrict__ f1b,
                      const float* __restrict__ f2w, const float* __restrict__ f2b,
                      const float* __restrict__ cw, const float* __restrict__ cb) {
    if (threadIdx.x != 0 || blockIdx.x != 0) return;
    float mean[6];
    #pragma unroll
    for (int c = 0; c < 6; c++) mean[c] = d_sums[c] * (1.0f / 6400000.0f);
    float a1[30];
    for (int i = 0; i < 30; i++) {
        float s = f1b[i];
        #pragma unroll
        for (int c = 0; c < 6; c++) s += mean[c] * f1w[i * 6 + c];
        a1[i] = fmaxf(s, 0.0f);
    }
    for (int c = 0; c < 6; c++) {
        float s = f2b[c];
        for (int i = 0; i < 30; i++) s += a1[i] * f2w[c * 30 + i];
        float sg = 1.0f / (1.0f + expf(-s));
        // relu(att*XM) == att*XM since XM>=0, att>0 -> fold att into conv_w
        d_coef[c] = sg * cw[c];
    }
    d_coef[6] = cb[0];
}

// ---------------- final: out[n,d] = cb + sum_c coef[c]*XM[c*64N + d*N + n] -----
__global__ void k_final(float* __restrict__ out) {
    int n = blockIdx.x * blockDim.x + threadIdx.x;
    if (n >= NN) return;
    float cf[6];
    #pragma unroll
    for (int c = 0; c < 6; c++) cf[c] = d_coef[c];
    float cb = d_coef[6];
    #pragma unroll 4
    for (int d = 0; d < 64; d++) {
        float v = cb;
        int base = d * NN + n;
        #pragma unroll
        for (int c = 0; c < 6; c++)
            v += cf[c] * d_xm[(size_t)c * CHUNK + base];
        out[n * 64 + d] = v;
    }
}

// ---------------- launcher ----------------
extern "C" void kernel_launch(void* const* d_in, const int* in_sizes, int n_in,
                              void* d_out, int out_size) {
    // Detect input ordering: setup_inputs dict order vs. reference signature order.
    int iWg, iWc, iWf, iEg, iEc, iEf, iW1, ib1, iW2, ib2, if1w, if1b, if2w, if2b, icw, icb;
    if (in_sizes[4] == 6400000) {  // dict order: x, w_g,w_c,w_f, edges_g,c,f, W1,b1,W2,b2, fc..., conv...
        iWg = 1; iWc = 2; iWf = 3; iEg = 4; iEc = 5; iEf = 6;
        iW1 = 7; ib1 = 8; iW2 = 9; ib2 = 10;
        if1w = 11; if1b = 12; if2w = 13; if2b = 14; icw = 15; icb = 16;
    } else {                       // signature order: x, w_g,w_c,w_f, W1,b1,W2,b2, fc..., conv..., edges_g,c,f
        iWg = 1; iWc = 2; iWf = 3;
        iW1 = 4; ib1 = 5; iW2 = 6; ib2 = 7;
        if1w = 8; if1b = 9; if2w = 10; if2b = 11; icw = 12; icb = 13;
        iEg = 14; iEc = 15; iEf = 16;
    }

    const float* x  = (const float*)d_in[0];
    const float* ews[3] = { (const float*)d_in[iWg], (const float*)d_in[iWc], (const float*)d_in[iWf] };
    const int*   eis[3] = { (const int*)d_in[iEg],   (const int*)d_in[iEc],   (const int*)d_in[iEf] };
    const float* W1 = (const float*)d_in[iW1];
    const float* b1 = (const float*)d_in[ib1];
    const float* W2 = (const float*)d_in[iW2];
    const float* b2 = (const float*)d_in[ib2];

    const int GB_N   = (NN + 255) / 256;          // 391
    const int GB_E   = (EE + 255) / 256;          // 12500
    const int GB_NF  = (NN * 64) / 256;           // 25000
    const int GB_SC  = (EE * 16) / 256;           // 200000
    const int GB_GM  = (NN + 127) / 128;          // 782

    for (int g = 0; g < 3; g++) {
        // graph norm build
        k_init_deg<<<GB_N, 256>>>();
        k_deg<<<GB_E, 256>>>(eis[g], ews[g]);
        k_dinv<<<GB_N, 256>>>();
        k_norm<<<GB_E, 256>>>(eis[g], ews[g]);

        // layer 1: h = x @ W1 ; scatter ; epi -> xm[:, g*128 .. g*128+63]
        k_gemm<<<GB_GM, 256>>>(x, 64, 0, W1);
        k_zero_acc<<<GB_NF, 256>>>();
        k_scatter<<<GB_SC, 256>>>(eis[g]);
        k_epi<<<GB_NF, 256>>>(b1, g * 128);

        // layer 2: h = g1 @ W2 ; scatter ; epi -> xm[:, g*128+64 ..]
        k_gemm<<<GB_GM, 256>>>(nullptr, 384, g * 128, W2);
        k_zero_acc<<<GB_NF, 256>>>();
        k_scatter<<<GB_SC, 256>>>(eis[g]);
        k_epi<<<GB_NF, 256>>>(b2, g * 128 + 64);
    }

    // attention + output
    k_zero_sums<<<1, 32>>>();
    k_chunksum<<<2048, 256>>>();
    k_att<<<1, 32>>>((const float*)d_in[if1w], (const float*)d_in[if1b],
                     (const float*)d_in[if2w], (const float*)d_in[if2b],
                     (const float*)d_in[icw],  (const float*)d_in[icb]);
    k_final<<<GB_GM, 128>>>((float*)d_out);
}